// round 5
// baseline (speedup 1.0000x reference)
#include <cuda_runtime.h>
#include <cuda_bf16.h>
#include <cuda_fp16.h>
#include <cstdint>

#define D_DIM   128
#define NPOS    512
#define K_DIM   2048
#define R_MAX   49152    // B*H*Q = 2*12*2048
#define NCHUNK  8
#define CH_ROWS (R_MAX / NCHUNK)   // 6144

// 50 MB scratch: fp16 interpolation tables (512 entries per (b,h,q) row).
__device__ __half g_table[(size_t)R_MAX * NPOS];

// ---------------------------------------------------------------------------
// mma.sync m16n8k16 row.col f32.bf16.bf16.f32  (tensor pipe, sm_80+ PTX)
// ---------------------------------------------------------------------------
__device__ __forceinline__ void mma_bf16(float* d, const uint32_t* a, const uint32_t* b) {
    asm volatile(
        "mma.sync.aligned.m16n8k16.row.col.f32.bf16.bf16.f32 "
        "{%0,%1,%2,%3}, {%4,%5,%6,%7}, {%8,%9}, {%0,%1,%2,%3};"
        : "+f"(d[0]), "+f"(d[1]), "+f"(d[2]), "+f"(d[3])
        : "r"(a[0]), "r"(a[1]), "r"(a[2]), "r"(a[3]), "r"(b[0]), "r"(b[1]));
}

__device__ __forceinline__ void ldsm_x4(uint32_t* r, uint32_t addr) {
    asm volatile("ldmatrix.sync.aligned.m8n8.x4.shared.b16 {%0,%1,%2,%3}, [%4];"
        : "=r"(r[0]), "=r"(r[1]), "=r"(r[2]), "=r"(r[3]) : "r"(addr));
}
__device__ __forceinline__ void ldsm_x4_t(uint32_t* r, uint32_t addr) {
    asm volatile("ldmatrix.sync.aligned.m8n8.x4.trans.shared.b16 {%0,%1,%2,%3}, [%4];"
        : "=r"(r[0]), "=r"(r[1]), "=r"(r[2]), "=r"(r[3]) : "r"(addr));
}

__device__ __forceinline__ uint32_t smem_u32(const void* p) {
    uint32_t a;
    asm("{ .reg .u64 t; cvta.to.shared.u64 t, %1; cvt.u32.u64 %0, t; }" : "=r"(a) : "l"(p));
    return a;
}

__device__ __forceinline__ uint32_t pack_bf16(float a, float b) {
    __nv_bfloat162 t = __floats2bfloat162_rn(a, b);
    return *reinterpret_cast<uint32_t*>(&t);
}

// ============================================================================
// Kernel A: T[rows,512] = Q[rows,128] @ P[128,512], bf16x3 split (chunked).
// Block 128x128 tile, 8 warps (4M x 2N), warp tile m32 x n64, ldmatrix loads.
// ============================================================================
#define SSTR      272           // smem row stride in bytes
#define SM_A_HI   0
#define SM_A_LO   34816         // 128*272
#define SM_B_HI   69632
#define SM_B_LO   104448
#define SM_TOTAL  139264

__global__ __launch_bounds__(256, 1)
void cope_gemm_mma(const float* __restrict__ Q,   // [R,128]
                   const float* __restrict__ P,   // [128,512]
                   int r_base) {
    extern __shared__ char sm[];
    const int tid  = threadIdx.x;
    const int lane = tid & 31;
    const int wid  = tid >> 5;
    const int r0   = r_base + blockIdx.y * 128;
    const int n0   = blockIdx.x * 128;

    // ---- load A tile: 128 rows x K=128, split bf16 hi/lo, [m][k] ----
    {
        int r  = tid >> 1;
        int c0 = (tid & 1) * 64;
        const float4* src = (const float4*)(Q + (size_t)(r0 + r) * D_DIM + c0);
        char* dhi = sm + SM_A_HI + r * SSTR + c0 * 2;
        char* dlo = sm + SM_A_LO + r * SSTR + c0 * 2;
        #pragma unroll
        for (int i = 0; i < 16; i++) {
            float4 v = src[i];
            float x[4] = {v.x, v.y, v.z, v.w};
            float hi[4], lo[4];
            #pragma unroll
            for (int j = 0; j < 4; j++) {
                hi[j] = __bfloat162float(__float2bfloat16(x[j]));
                lo[j] = x[j] - hi[j];
            }
            uint2 whi, wlo;
            whi.x = pack_bf16(hi[0], hi[1]); whi.y = pack_bf16(hi[2], hi[3]);
            wlo.x = pack_bf16(lo[0], lo[1]); wlo.y = pack_bf16(lo[2], lo[3]);
            *(uint2*)(dhi + i * 8) = whi;
            *(uint2*)(dlo + i * 8) = wlo;
        }
    }

    // ---- load B tile k-major: sB[k][n] = P[k][n0+n], split hi/lo ----
    {
        int k  = tid >> 1;
        int c0 = (tid & 1) * 64;
        const float4* src = (const float4*)(P + (size_t)k * NPOS + n0 + c0);
        char* dhi = sm + SM_B_HI + k * SSTR + c0 * 2;
        char* dlo = sm + SM_B_LO + k * SSTR + c0 * 2;
        #pragma unroll
        for (int i = 0; i < 16; i++) {
            float4 v = src[i];
            float x[4] = {v.x, v.y, v.z, v.w};
            float hi[4], lo[4];
            #pragma unroll
            for (int j = 0; j < 4; j++) {
                hi[j] = __bfloat162float(__float2bfloat16(x[j]));
                lo[j] = x[j] - hi[j];
            }
            uint2 whi, wlo;
            whi.x = pack_bf16(hi[0], hi[1]); whi.y = pack_bf16(hi[2], hi[3]);
            wlo.x = pack_bf16(lo[0], lo[1]); wlo.y = pack_bf16(lo[2], lo[3]);
            *(uint2*)(dhi + i * 8) = whi;
            *(uint2*)(dlo + i * 8) = wlo;
        }
    }
    __syncthreads();

    const int g = lane >> 2;           // 0..7
    const int t = lane & 3;            // 0..3
    const int mrow = (wid & 3) * 32;
    const int ncol = (wid >> 2) * 64;

    const uint32_t smb = smem_u32(sm);
    const uint32_t a_off = (uint32_t)((mrow + ((lane >> 3) & 1) * 8 + (lane & 7)) * SSTR
                                      + (lane >> 4) * 16);
    const uint32_t b_off = (uint32_t)((((lane >> 3) & 1) * 8 + (lane & 7)) * SSTR
                                      + (lane >> 4) * 16 + ncol * 2);

    float acc[2][8][4];
    #pragma unroll
    for (int mf = 0; mf < 2; mf++)
        #pragma unroll
        for (int nf = 0; nf < 8; nf++)
            #pragma unroll
            for (int c = 0; c < 4; c++) acc[mf][nf][c] = 0.0f;

    #pragma unroll
    for (int ks = 0; ks < 8; ks++) {
        const uint32_t kb = ks * 32;
        uint32_t ahi[2][4], alo[2][4];
        #pragma unroll
        for (int mf = 0; mf < 2; mf++) {
            ldsm_x4(ahi[mf], smb + SM_A_HI + mf * 16 * SSTR + a_off + kb);
            ldsm_x4(alo[mf], smb + SM_A_LO + mf * 16 * SSTR + a_off + kb);
        }
        uint32_t bhi[4][4], blo[4][4];
        #pragma unroll
        for (int p = 0; p < 4; p++) {
            ldsm_x4_t(bhi[p], smb + SM_B_HI + ks * 16 * SSTR + b_off + p * 32);
            ldsm_x4_t(blo[p], smb + SM_B_LO + ks * 16 * SSTR + b_off + p * 32);
        }
        #pragma unroll
        for (int mf = 0; mf < 2; mf++) {
            #pragma unroll
            for (int p = 0; p < 4; p++) {
                mma_bf16(acc[mf][2 * p],     ahi[mf], &bhi[p][0]);
                mma_bf16(acc[mf][2 * p + 1], ahi[mf], &bhi[p][2]);
                mma_bf16(acc[mf][2 * p],     ahi[mf], &blo[p][0]);
                mma_bf16(acc[mf][2 * p + 1], ahi[mf], &blo[p][2]);
                mma_bf16(acc[mf][2 * p],     alo[mf], &bhi[p][0]);
                mma_bf16(acc[mf][2 * p + 1], alo[mf], &bhi[p][2]);
            }
        }
    }

    // ---- epilogue: pack (c0,c1)/(c2,c3) column pairs as half2 ----
    #pragma unroll
    for (int mf = 0; mf < 2; mf++) {
        #pragma unroll
        for (int nf = 0; nf < 8; nf++) {
            size_t row = (size_t)(r0 + mrow + mf * 16 + g);
            size_t nn  = (size_t)(n0 + ncol + nf * 8 + t * 2);
            __half2 h0 = __floats2half2_rn(acc[mf][nf][0], acc[mf][nf][1]);
            __half2 h1 = __floats2half2_rn(acc[mf][nf][2], acc[mf][nf][3]);
            *(uint32_t*)(g_table + row * NPOS + nn)        = *(uint32_t*)&h0;
            *(uint32_t*)(g_table + (row + 8) * NPOS + nn)  = *(uint32_t*)&h1;
        }
    }
}

// ============================================================================
// Kernel B: per row — sigmoid, reversed cumsum, clamp, interp gather (chunked).
// ============================================================================
__global__ __launch_bounds__(256)
void cope_gather_kernel(const float* __restrict__ attn,   // [R,2048]
                        const int*   __restrict__ nposp,
                        float*       __restrict__ out,    // [R,2048]
                        int row_base) {
    __shared__ __half    tabh[NPOS];
    __shared__ uint32_t  tab2u[NPOS];
    __shared__ float     wsum[8];

    const int row  = row_base + blockIdx.x;
    const int tid  = threadIdx.x;
    const int lane = tid & 31;
    const int wid  = tid >> 5;

    ((uint32_t*)tabh)[tid] =
        ((const uint32_t*)(g_table + (size_t)row * NPOS))[tid];

    const float* arow = attn + (size_t)row * K_DIM + tid * 8;
    float4 v0 = *(const float4*)(arow);
    float4 v1 = *(const float4*)(arow + 4);
    float gg[8] = {v0.x, v0.y, v0.z, v0.w, v1.x, v1.y, v1.z, v1.w};
    #pragma unroll
    for (int j = 0; j < 8; j++)
        gg[j] = __fdividef(1.0f, 1.0f + __expf(-gg[j]));

    __syncthreads();
    {
        __half a = tabh[tid], b = tabh[tid + 1];
        __half2 h; h.x = a; h.y = b;
        tab2u[tid] = *(uint32_t*)&h;
        int i2 = tid + 256;
        __half a2 = tabh[i2];
        __half b2 = (i2 == NPOS - 1) ? a2 : tabh[i2 + 1];
        __half2 h2; h2.x = a2; h2.y = b2;
        tab2u[i2] = *(uint32_t*)&h2;
    }

    float ls[8];
    ls[7] = gg[7];
    #pragma unroll
    for (int j = 6; j >= 0; j--) ls[j] = gg[j] + ls[j + 1];

    float v = ls[0];
    #pragma unroll
    for (int d = 1; d < 32; d <<= 1) {
        float tt = __shfl_up_sync(0xffffffffu, v, d);
        if (lane >= d) v += tt;
    }
    if (lane == 31) wsum[wid] = v;
    __syncthreads();

    float wpre = 0.0f, total = 0.0f;
    #pragma unroll
    for (int w = 0; w < 8; w++) {
        float x = wsum[w];
        total += x;
        if (w < wid) wpre += x;
    }
    float offset = total - (wpre + v);

    const float npmf = (float)(*nposp - 1);

    float oo[8];
    #pragma unroll
    for (int j = 0; j < 8; j++) {
        float p  = fminf(offset + ls[j], npmf);
        float pf = floorf(p);
        float w  = p - pf;
        uint32_t pv = tab2u[(int)pf];
        float2 f = __half22float2(*(__half2*)&pv);
        oo[j] = fmaf(w, f.y - f.x, f.x);
    }

    float* orow = out + (size_t)row * K_DIM + tid * 8;
    *(float4*)(orow)     = make_float4(oo[0], oo[1], oo[2], oo[3]);
    *(float4*)(orow + 4) = make_float4(oo[4], oo[5], oo[6], oo[7]);
}

// ---------------------------------------------------------------------------
// Chunked two-stream pipeline: gather_i depends only on gemm_i, so gather_i
// overlaps gemm_{i+1}. Streams/events created once on the first (uncaptured)
// correctness call; replayed identically under graph capture (fork/join).
// ---------------------------------------------------------------------------
extern "C" void kernel_launch(void* const* d_in, const int* in_sizes, int n_in,
                              void* d_out, int out_size) {
    const float* q    = (const float*)d_in[0];   // [B,H,Q,D]
    const float* attn = (const float*)d_in[1];   // [B,H,Q,K]
    const float* pe   = (const float*)d_in[2];   // [1,D,NPOS]
    const int*   npos = (const int*)d_in[3];
    float*       out  = (float*)d_out;

    static cudaStream_t s_g = nullptr, s_h = nullptr;
    static cudaEvent_t  evStart, evFin;
    static cudaEvent_t  evG[NCHUNK];
    static bool         inited = false;
    if (!inited) {
        cudaStreamCreateWithFlags(&s_g, cudaStreamNonBlocking);
        cudaStreamCreateWithFlags(&s_h, cudaStreamNonBlocking);
        cudaEventCreateWithFlags(&evStart, cudaEventDisableTiming);
        cudaEventCreateWithFlags(&evFin,   cudaEventDisableTiming);
        for (int i = 0; i < NCHUNK; i++)
            cudaEventCreateWithFlags(&evG[i], cudaEventDisableTiming);
        cudaFuncSetAttribute(cope_gemm_mma,
                             cudaFuncAttributeMaxDynamicSharedMemorySize, SM_TOTAL);
        inited = true;
    }

    // fork from the (captured) default stream
    cudaEventRecord(evStart, 0);
    cudaStreamWaitEvent(s_g, evStart, 0);
    cudaStreamWaitEvent(s_h, evStart, 0);

    dim3 gA(NPOS / 128, CH_ROWS / 128);
    for (int i = 0; i < NCHUNK; i++) {
        int r0 = i * CH_ROWS;
        cope_gemm_mma<<<gA, 256, SM_TOTAL, s_g>>>(q, pe, r0);
        cudaEventRecord(evG[i], s_g);
        cudaStreamWaitEvent(s_h, evG[i], 0);
        cope_gather_kernel<<<CH_ROWS, 256, 0, s_h>>>(attn, npos, out, r0);
    }

    // join back to the default stream
    cudaEventRecord(evFin, s_h);
    cudaStreamWaitEvent(0, evFin, 0);

    (void)n_in; (void)out_size;
}

// round 6
// speedup vs baseline: 1.1476x; 1.1476x over previous
#include <cuda_runtime.h>
#include <cuda_bf16.h>
#include <cuda_fp16.h>
#include <cstdint>

#define D_DIM   128
#define NPOS    512
#define K_DIM   2048
#define R_MAX   49152    // B*H*Q = 2*12*2048

// 50 MB scratch: fp16 interpolation tables (512 entries per (b,h,q) row).
__device__ __half g_table[(size_t)R_MAX * NPOS];

// ---------------------------------------------------------------------------
// mma.sync m16n8k16 row.col f32.bf16.bf16.f32  (tensor pipe, sm_80+ PTX)
// ---------------------------------------------------------------------------
__device__ __forceinline__ void mma_bf16(float* d, const uint32_t* a, const uint32_t* b) {
    asm volatile(
        "mma.sync.aligned.m16n8k16.row.col.f32.bf16.bf16.f32 "
        "{%0,%1,%2,%3}, {%4,%5,%6,%7}, {%8,%9}, {%0,%1,%2,%3};"
        : "+f"(d[0]), "+f"(d[1]), "+f"(d[2]), "+f"(d[3])
        : "r"(a[0]), "r"(a[1]), "r"(a[2]), "r"(a[3]), "r"(b[0]), "r"(b[1]));
}

__device__ __forceinline__ void ldsm_x4(uint32_t* r, uint32_t addr) {
    asm volatile("ldmatrix.sync.aligned.m8n8.x4.shared.b16 {%0,%1,%2,%3}, [%4];"
        : "=r"(r[0]), "=r"(r[1]), "=r"(r[2]), "=r"(r[3]) : "r"(addr));
}
__device__ __forceinline__ void ldsm_x4_t(uint32_t* r, uint32_t addr) {
    asm volatile("ldmatrix.sync.aligned.m8n8.x4.trans.shared.b16 {%0,%1,%2,%3}, [%4];"
        : "=r"(r[0]), "=r"(r[1]), "=r"(r[2]), "=r"(r[3]) : "r"(addr));
}

__device__ __forceinline__ uint32_t smem_u32(const void* p) {
    uint32_t a;
    asm("{ .reg .u64 t; cvta.to.shared.u64 t, %1; cvt.u32.u64 %0, t; }" : "=r"(a) : "l"(p));
    return a;
}

__device__ __forceinline__ uint32_t pack_bf16(float a, float b) {
    __nv_bfloat162 t = __floats2bfloat162_rn(a, b);
    return *reinterpret_cast<uint32_t*>(&t);
}

// ============================================================================
// Kernel A: T[R,512] = Q[R,128] @ P[128,512], bf16x3 split precision.
// Block 64(M) x 128(N) tile, 8 warps (2M x 4N), warp tile m32 x n32.
// smem 104.4 KB -> 2 blocks/SM (4 warps/SMSP). MMA issued in 3 component
// passes (8 independent HMMAs between accumulator reuses).
// ============================================================================
#define SSTR      272           // smem row stride in bytes (conflict-free)
#define SM_A_HI   0
#define SM_A_LO   17408         // 64*272
#define SM_B_HI   34816
#define SM_B_LO   69632         // 34816 + 128*272
#define SM_TOTAL  104448

__global__ __launch_bounds__(256, 2)
void cope_gemm_mma(const float* __restrict__ Q,   // [R,128]
                   const float* __restrict__ P) { // [128,512]
    extern __shared__ char sm[];
    const int tid  = threadIdx.x;
    const int lane = tid & 31;
    const int wid  = tid >> 5;
    const int r0   = blockIdx.y * 64;
    const int n0   = blockIdx.x * 128;

    // ---- load A tile: 64 rows x K=128, split bf16 hi/lo, [m][k] ----
    {
        int r  = tid >> 2;               // 0..63
        int c0 = (tid & 3) * 32;         // 32 k-floats per thread
        const float4* src = (const float4*)(Q + (size_t)(r0 + r) * D_DIM + c0);
        char* dhi = sm + SM_A_HI + r * SSTR + c0 * 2;
        char* dlo = sm + SM_A_LO + r * SSTR + c0 * 2;
        #pragma unroll
        for (int i = 0; i < 8; i++) {
            float4 v = src[i];
            float x[4] = {v.x, v.y, v.z, v.w};
            float hi[4], lo[4];
            #pragma unroll
            for (int j = 0; j < 4; j++) {
                hi[j] = __bfloat162float(__float2bfloat16(x[j]));
                lo[j] = x[j] - hi[j];
            }
            uint2 whi, wlo;
            whi.x = pack_bf16(hi[0], hi[1]); whi.y = pack_bf16(hi[2], hi[3]);
            wlo.x = pack_bf16(lo[0], lo[1]); wlo.y = pack_bf16(lo[2], lo[3]);
            *(uint2*)(dhi + i * 8) = whi;
            *(uint2*)(dlo + i * 8) = wlo;
        }
    }

    // ---- load B tile k-major: sB[k][n] = P[k][n0+n], split hi/lo ----
    {
        int k  = tid >> 1;               // 0..127
        int c0 = (tid & 1) * 64;
        const float4* src = (const float4*)(P + (size_t)k * NPOS + n0 + c0);
        char* dhi = sm + SM_B_HI + k * SSTR + c0 * 2;
        char* dlo = sm + SM_B_LO + k * SSTR + c0 * 2;
        #pragma unroll
        for (int i = 0; i < 16; i++) {
            float4 v = src[i];
            float x[4] = {v.x, v.y, v.z, v.w};
            float hi[4], lo[4];
            #pragma unroll
            for (int j = 0; j < 4; j++) {
                hi[j] = __bfloat162float(__float2bfloat16(x[j]));
                lo[j] = x[j] - hi[j];
            }
            uint2 whi, wlo;
            whi.x = pack_bf16(hi[0], hi[1]); whi.y = pack_bf16(hi[2], hi[3]);
            wlo.x = pack_bf16(lo[0], lo[1]); wlo.y = pack_bf16(lo[2], lo[3]);
            *(uint2*)(dhi + i * 8) = whi;
            *(uint2*)(dlo + i * 8) = wlo;
        }
    }
    __syncthreads();

    const int g = lane >> 2;             // 0..7
    const int t = lane & 3;              // 0..3
    const int mrow = (wid & 1) * 32;     // 2 warps along M
    const int ncol = (wid >> 1) * 32;    // 4 warps along N

    const uint32_t smb = smem_u32(sm);
    const uint32_t a_off = (uint32_t)((mrow + ((lane >> 3) & 1) * 8 + (lane & 7)) * SSTR
                                      + (lane >> 4) * 16);
    const uint32_t b_off = (uint32_t)((((lane >> 3) & 1) * 8 + (lane & 7)) * SSTR
                                      + (lane >> 4) * 16 + ncol * 2);

    float acc[2][4][4];                  // [mf][nf][c]
    #pragma unroll
    for (int mf = 0; mf < 2; mf++)
        #pragma unroll
        for (int nf = 0; nf < 4; nf++)
            #pragma unroll
            for (int c = 0; c < 4; c++) acc[mf][nf][c] = 0.0f;

    #pragma unroll
    for (int ks = 0; ks < 8; ks++) {
        const uint32_t kb = ks * 32;
        uint32_t ahi[2][4], alo[2][4];
        #pragma unroll
        for (int mf = 0; mf < 2; mf++) {
            ldsm_x4(ahi[mf], smb + SM_A_HI + mf * 16 * SSTR + a_off + kb);
            ldsm_x4(alo[mf], smb + SM_A_LO + mf * 16 * SSTR + a_off + kb);
        }
        uint32_t bhi[2][4], blo[2][4];   // p covers nf=2p, 2p+1
        #pragma unroll
        for (int p = 0; p < 2; p++) {
            ldsm_x4_t(bhi[p], smb + SM_B_HI + ks * 16 * SSTR + b_off + p * 32);
            ldsm_x4_t(blo[p], smb + SM_B_LO + ks * 16 * SSTR + b_off + p * 32);
        }
        // pass 1: Ahi*Bhi over all 8 acc tiles (independent)
        #pragma unroll
        for (int mf = 0; mf < 2; mf++)
            #pragma unroll
            for (int p = 0; p < 2; p++) {
                mma_bf16(acc[mf][2 * p],     ahi[mf], &bhi[p][0]);
                mma_bf16(acc[mf][2 * p + 1], ahi[mf], &bhi[p][2]);
            }
        // pass 2: Ahi*Blo
        #pragma unroll
        for (int mf = 0; mf < 2; mf++)
            #pragma unroll
            for (int p = 0; p < 2; p++) {
                mma_bf16(acc[mf][2 * p],     ahi[mf], &blo[p][0]);
                mma_bf16(acc[mf][2 * p + 1], ahi[mf], &blo[p][2]);
            }
        // pass 3: Alo*Bhi
        #pragma unroll
        for (int mf = 0; mf < 2; mf++)
            #pragma unroll
            for (int p = 0; p < 2; p++) {
                mma_bf16(acc[mf][2 * p],     alo[mf], &bhi[p][0]);
                mma_bf16(acc[mf][2 * p + 1], alo[mf], &bhi[p][2]);
            }
    }

    // ---- epilogue: pack (c0,c1)/(c2,c3) column pairs as half2 ----
    #pragma unroll
    for (int mf = 0; mf < 2; mf++) {
        #pragma unroll
        for (int nf = 0; nf < 4; nf++) {
            size_t row = (size_t)(r0 + mrow + mf * 16 + g);
            size_t nn  = (size_t)(n0 + ncol + nf * 8 + t * 2);
            __half2 h0 = __floats2half2_rn(acc[mf][nf][0], acc[mf][nf][1]);
            __half2 h1 = __floats2half2_rn(acc[mf][nf][2], acc[mf][nf][3]);
            *(uint32_t*)(g_table + row * NPOS + nn)        = *(uint32_t*)&h0;
            *(uint32_t*)(g_table + (row + 8) * NPOS + nn)  = *(uint32_t*)&h1;
        }
    }
}

// ============================================================================
// Kernel B: per row — sigmoid, reversed cumsum, clamp, interp gather.
// Table staged as half2 pairs (t[i], t[i+1]) -> one LDS.32 per element.
// ============================================================================
__global__ __launch_bounds__(256)
void cope_gather_kernel(const float* __restrict__ attn,   // [R,2048]
                        const int*   __restrict__ nposp,
                        float*       __restrict__ out) {  // [R,2048]
    __shared__ __half    tabh[NPOS];
    __shared__ uint32_t  tab2u[NPOS];
    __shared__ float     wsum[8];

    const int row  = blockIdx.x;
    const int tid  = threadIdx.x;
    const int lane = tid & 31;
    const int wid  = tid >> 5;

    ((uint32_t*)tabh)[tid] =
        ((const uint32_t*)(g_table + (size_t)row * NPOS))[tid];

    const float* arow = attn + (size_t)row * K_DIM + tid * 8;
    float4 v0 = *(const float4*)(arow);
    float4 v1 = *(const float4*)(arow + 4);
    float gg[8] = {v0.x, v0.y, v0.z, v0.w, v1.x, v1.y, v1.z, v1.w};
    #pragma unroll
    for (int j = 0; j < 8; j++)
        gg[j] = __fdividef(1.0f, 1.0f + __expf(-gg[j]));

    __syncthreads();
    {
        __half a = tabh[tid], b = tabh[tid + 1];
        __half2 h; h.x = a; h.y = b;
        tab2u[tid] = *(uint32_t*)&h;
        int i2 = tid + 256;
        __half a2 = tabh[i2];
        __half b2 = (i2 == NPOS - 1) ? a2 : tabh[i2 + 1];
        __half2 h2; h2.x = a2; h2.y = b2;
        tab2u[i2] = *(uint32_t*)&h2;
    }

    float ls[8];
    ls[7] = gg[7];
    #pragma unroll
    for (int j = 6; j >= 0; j--) ls[j] = gg[j] + ls[j + 1];

    float v = ls[0];
    #pragma unroll
    for (int d = 1; d < 32; d <<= 1) {
        float tt = __shfl_up_sync(0xffffffffu, v, d);
        if (lane >= d) v += tt;
    }
    if (lane == 31) wsum[wid] = v;
    __syncthreads();

    float wpre = 0.0f, total = 0.0f;
    #pragma unroll
    for (int w = 0; w < 8; w++) {
        float x = wsum[w];
        total += x;
        if (w < wid) wpre += x;
    }
    float offset = total - (wpre + v);

    const float npmf = (float)(*nposp - 1);

    float oo[8];
    #pragma unroll
    for (int j = 0; j < 8; j++) {
        float p  = fminf(offset + ls[j], npmf);
        float pf = floorf(p);
        float w  = p - pf;
        uint32_t pv = tab2u[(int)pf];
        float2 f = __half22float2(*(__half2*)&pv);
        oo[j] = fmaf(w, f.y - f.x, f.x);
    }

    float* orow = out + (size_t)row * K_DIM + tid * 8;
    *(float4*)(orow)     = make_float4(oo[0], oo[1], oo[2], oo[3]);
    *(float4*)(orow + 4) = make_float4(oo[4], oo[5], oo[6], oo[7]);
}

// ---------------------------------------------------------------------------
extern "C" void kernel_launch(void* const* d_in, const int* in_sizes, int n_in,
                              void* d_out, int out_size) {
    const float* q    = (const float*)d_in[0];   // [B,H,Q,D]
    const float* attn = (const float*)d_in[1];   // [B,H,Q,K]
    const float* pe   = (const float*)d_in[2];   // [1,D,NPOS]
    const int*   npos = (const int*)d_in[3];
    float*       out  = (float*)d_out;

    const int R = in_sizes[0] / D_DIM;           // 49152

    cudaFuncSetAttribute(cope_gemm_mma,
                         cudaFuncAttributeMaxDynamicSharedMemorySize, SM_TOTAL);
    dim3 gA(NPOS / 128, R / 64);
    cope_gemm_mma<<<gA, 256, SM_TOTAL>>>(q, pe);

    cope_gather_kernel<<<R, 256>>>(attn, npos, out);

    (void)n_in; (void)out_size;
}

// round 7
// speedup vs baseline: 1.2222x; 1.0651x over previous
#include <cuda_runtime.h>
#include <cuda_bf16.h>
#include <cuda_fp16.h>
#include <cstdint>

#define D_DIM   128
#define NPOS    512
#define K_DIM   2048
#define R_MAX   49152    // B*H*Q = 2*12*2048

// 50 MB scratch: fp16 interpolation tables (512 entries per (b,h,q) row).
__device__ __half g_table[(size_t)R_MAX * NPOS];

// ---------------------------------------------------------------------------
// mma.sync m16n8k16 row.col f32.bf16.bf16.f32  (tensor pipe, sm_80+ PTX)
// ---------------------------------------------------------------------------
__device__ __forceinline__ void mma_bf16(float* d, const uint32_t* a, const uint32_t* b) {
    asm volatile(
        "mma.sync.aligned.m16n8k16.row.col.f32.bf16.bf16.f32 "
        "{%0,%1,%2,%3}, {%4,%5,%6,%7}, {%8,%9}, {%0,%1,%2,%3};"
        : "+f"(d[0]), "+f"(d[1]), "+f"(d[2]), "+f"(d[3])
        : "r"(a[0]), "r"(a[1]), "r"(a[2]), "r"(a[3]), "r"(b[0]), "r"(b[1]));
}

__device__ __forceinline__ void ldsm_x4(uint32_t* r, uint32_t addr) {
    asm volatile("ldmatrix.sync.aligned.m8n8.x4.shared.b16 {%0,%1,%2,%3}, [%4];"
        : "=r"(r[0]), "=r"(r[1]), "=r"(r[2]), "=r"(r[3]) : "r"(addr));
}
__device__ __forceinline__ void ldsm_x4_t(uint32_t* r, uint32_t addr) {
    asm volatile("ldmatrix.sync.aligned.m8n8.x4.trans.shared.b16 {%0,%1,%2,%3}, [%4];"
        : "=r"(r[0]), "=r"(r[1]), "=r"(r[2]), "=r"(r[3]) : "r"(addr));
}

__device__ __forceinline__ uint32_t smem_u32(const void* p) {
    uint32_t a;
    asm("{ .reg .u64 t; cvta.to.shared.u64 t, %1; cvt.u32.u64 %0, t; }" : "=r"(a) : "l"(p));
    return a;
}

__device__ __forceinline__ uint32_t pack_bf16(float a, float b) {
    __nv_bfloat162 t = __floats2bfloat162_rn(a, b);
    return *reinterpret_cast<uint32_t*>(&t);
}

// ============================================================================
// Kernel A: T[R,512] = Q[R,128] @ P[128,512], bf16x3 split precision.
// Block 128(M) x 256(N), 512 threads, 16 warps (4M x 4N), warp tile m32 x n64.
// smem 200 KB (occ 1, 4 warps/SMSP). A [m][k] stride 272 B, B [k][n] stride
// 528 B (both stride%128B = 16 -> ldmatrix conflict-free).
// Component order hi*hi -> lo*hi -> hi*lo caps the live fragment set.
// ============================================================================
#define SSTR_A    272
#define SSTR_B    528
#define SM_A_HI   0
#define SM_A_LO   34816          // 128*272
#define SM_B_HI   69632
#define SM_B_LO   137216         // 69632 + 128*528
#define SM_TOTAL  204800         // 137216 + 128*528

__global__ __launch_bounds__(512, 1)
void cope_gemm_mma(const float* __restrict__ Q,   // [R,128]
                   const float* __restrict__ P) { // [128,512]
    extern __shared__ char sm[];
    const int tid  = threadIdx.x;
    const int lane = tid & 31;
    const int wid  = tid >> 5;
    const int r0   = blockIdx.y * 128;
    const int n0   = blockIdx.x * 256;

    // ---- load A tile: 128 rows x K=128, split bf16 hi/lo, [m][k] ----
    {
        int r  = tid >> 2;               // 0..127
        int c0 = (tid & 3) * 32;         // 32 k-floats per thread
        const float4* src = (const float4*)(Q + (size_t)(r0 + r) * D_DIM + c0);
        char* dhi = sm + SM_A_HI + r * SSTR_A + c0 * 2;
        char* dlo = sm + SM_A_LO + r * SSTR_A + c0 * 2;
        #pragma unroll
        for (int i = 0; i < 8; i++) {
            float4 v = src[i];
            float x[4] = {v.x, v.y, v.z, v.w};
            float hi[4], lo[4];
            #pragma unroll
            for (int j = 0; j < 4; j++) {
                hi[j] = __bfloat162float(__float2bfloat16(x[j]));
                lo[j] = x[j] - hi[j];
            }
            uint2 whi, wlo;
            whi.x = pack_bf16(hi[0], hi[1]); whi.y = pack_bf16(hi[2], hi[3]);
            wlo.x = pack_bf16(lo[0], lo[1]); wlo.y = pack_bf16(lo[2], lo[3]);
            *(uint2*)(dhi + i * 8) = whi;
            *(uint2*)(dlo + i * 8) = wlo;
        }
    }

    // ---- load B tile k-major: sB[k][n] = P[k][n0+n], 256 wide, split hi/lo ----
    {
        int k  = tid >> 2;               // 0..127
        int c0 = (tid & 3) * 64;         // 64 n-floats per thread
        const float4* src = (const float4*)(P + (size_t)k * NPOS + n0 + c0);
        char* dhi = sm + SM_B_HI + k * SSTR_B + c0 * 2;
        char* dlo = sm + SM_B_LO + k * SSTR_B + c0 * 2;
        #pragma unroll
        for (int i = 0; i < 16; i++) {
            float4 v = src[i];
            float x[4] = {v.x, v.y, v.z, v.w};
            float hi[4], lo[4];
            #pragma unroll
            for (int j = 0; j < 4; j++) {
                hi[j] = __bfloat162float(__float2bfloat16(x[j]));
                lo[j] = x[j] - hi[j];
            }
            uint2 whi, wlo;
            whi.x = pack_bf16(hi[0], hi[1]); whi.y = pack_bf16(hi[2], hi[3]);
            wlo.x = pack_bf16(lo[0], lo[1]); wlo.y = pack_bf16(lo[2], lo[3]);
            *(uint2*)(dhi + i * 8) = whi;
            *(uint2*)(dlo + i * 8) = wlo;
        }
    }
    __syncthreads();

    const int g = lane >> 2;             // 0..7
    const int t = lane & 3;              // 0..3
    const int mrow = (wid & 3) * 32;     // 4 warps along M
    const int ncol = (wid >> 2) * 64;    // 4 warps along N

    const uint32_t smb = smem_u32(sm);
    const uint32_t a_off = (uint32_t)((mrow + ((lane >> 3) & 1) * 8 + (lane & 7)) * SSTR_A
                                      + (lane >> 4) * 16);
    const uint32_t b_off = (uint32_t)((((lane >> 3) & 1) * 8 + (lane & 7)) * SSTR_B
                                      + (lane >> 4) * 16 + ncol * 2);

    float acc[2][8][4];                  // [mf][nf][c]
    #pragma unroll
    for (int mf = 0; mf < 2; mf++)
        #pragma unroll
        for (int nf = 0; nf < 8; nf++)
            #pragma unroll
            for (int c = 0; c < 4; c++) acc[mf][nf][c] = 0.0f;

    #pragma unroll
    for (int ks = 0; ks < 8; ks++) {
        const uint32_t kb = ks * 32;     // A byte offset along k
        uint32_t ahi[2][4], alo[2][4];
        #pragma unroll
        for (int mf = 0; mf < 2; mf++) {
            ldsm_x4(ahi[mf], smb + SM_A_HI + mf * 16 * SSTR_A + a_off + kb);
            ldsm_x4(alo[mf], smb + SM_A_LO + mf * 16 * SSTR_A + a_off + kb);
        }
        uint32_t bhi[4][4];              // p covers nf=2p, 2p+1
        #pragma unroll
        for (int p = 0; p < 4; p++)
            ldsm_x4_t(bhi[p], smb + SM_B_HI + ks * 16 * SSTR_B + b_off + p * 32);

        // pass 1: Ahi*Bhi   (8 independent HMMAs per mf-group)
        #pragma unroll
        for (int mf = 0; mf < 2; mf++)
            #pragma unroll
            for (int p = 0; p < 4; p++) {
                mma_bf16(acc[mf][2 * p],     ahi[mf], &bhi[p][0]);
                mma_bf16(acc[mf][2 * p + 1], ahi[mf], &bhi[p][2]);
            }
        // pass 2: Alo*Bhi   (bhi dies after this)
        #pragma unroll
        for (int mf = 0; mf < 2; mf++)
            #pragma unroll
            for (int p = 0; p < 4; p++) {
                mma_bf16(acc[mf][2 * p],     alo[mf], &bhi[p][0]);
                mma_bf16(acc[mf][2 * p + 1], alo[mf], &bhi[p][2]);
            }
        // pass 3: Ahi*Blo
        uint32_t blo[4][4];
        #pragma unroll
        for (int p = 0; p < 4; p++)
            ldsm_x4_t(blo[p], smb + SM_B_LO + ks * 16 * SSTR_B + b_off + p * 32);
        #pragma unroll
        for (int mf = 0; mf < 2; mf++)
            #pragma unroll
            for (int p = 0; p < 4; p++) {
                mma_bf16(acc[mf][2 * p],     ahi[mf], &blo[p][0]);
                mma_bf16(acc[mf][2 * p + 1], ahi[mf], &blo[p][2]);
            }
    }

    // ---- epilogue: pack (c0,c1)/(c2,c3) column pairs as half2 ----
    #pragma unroll
    for (int mf = 0; mf < 2; mf++) {
        #pragma unroll
        for (int nf = 0; nf < 8; nf++) {
            size_t row = (size_t)(r0 + mrow + mf * 16 + g);
            size_t nn  = (size_t)(n0 + ncol + nf * 8 + t * 2);
            __half2 h0 = __floats2half2_rn(acc[mf][nf][0], acc[mf][nf][1]);
            __half2 h1 = __floats2half2_rn(acc[mf][nf][2], acc[mf][nf][3]);
            *(uint32_t*)(g_table + row * NPOS + nn)        = *(uint32_t*)&h0;
            *(uint32_t*)(g_table + (row + 8) * NPOS + nn)  = *(uint32_t*)&h1;
        }
    }
}

// ============================================================================
// Kernel B: per row — sigmoid, reversed cumsum, clamp, interp gather.
// Table staged as half2 pairs (t[i], t[i+1]) -> one LDS.32 per element.
// ============================================================================
__global__ __launch_bounds__(256)
void cope_gather_kernel(const float* __restrict__ attn,   // [R,2048]
                        const int*   __restrict__ nposp,
                        float*       __restrict__ out) {  // [R,2048]
    __shared__ __half    tabh[NPOS];
    __shared__ uint32_t  tab2u[NPOS];
    __shared__ float     wsum[8];

    const int row  = blockIdx.x;
    const int tid  = threadIdx.x;
    const int lane = tid & 31;
    const int wid  = tid >> 5;

    ((uint32_t*)tabh)[tid] =
        ((const uint32_t*)(g_table + (size_t)row * NPOS))[tid];

    const float* arow = attn + (size_t)row * K_DIM + tid * 8;
    float4 v0 = *(const float4*)(arow);
    float4 v1 = *(const float4*)(arow + 4);
    float gg[8] = {v0.x, v0.y, v0.z, v0.w, v1.x, v1.y, v1.z, v1.w};
    #pragma unroll
    for (int j = 0; j < 8; j++)
        gg[j] = __fdividef(1.0f, 1.0f + __expf(-gg[j]));

    __syncthreads();
    {
        __half a = tabh[tid], b = tabh[tid + 1];
        __half2 h; h.x = a; h.y = b;
        tab2u[tid] = *(uint32_t*)&h;
        int i2 = tid + 256;
        __half a2 = tabh[i2];
        __half b2 = (i2 == NPOS - 1) ? a2 : tabh[i2 + 1];
        __half2 h2; h2.x = a2; h2.y = b2;
        tab2u[i2] = *(uint32_t*)&h2;
    }

    float ls[8];
    ls[7] = gg[7];
    #pragma unroll
    for (int j = 6; j >= 0; j--) ls[j] = gg[j] + ls[j + 1];

    float v = ls[0];
    #pragma unroll
    for (int d = 1; d < 32; d <<= 1) {
        float tt = __shfl_up_sync(0xffffffffu, v, d);
        if (lane >= d) v += tt;
    }
    if (lane == 31) wsum[wid] = v;
    __syncthreads();

    float wpre = 0.0f, total = 0.0f;
    #pragma unroll
    for (int w = 0; w < 8; w++) {
        float x = wsum[w];
        total += x;
        if (w < wid) wpre += x;
    }
    float offset = total - (wpre + v);

    const float npmf = (float)(*nposp - 1);

    float oo[8];
    #pragma unroll
    for (int j = 0; j < 8; j++) {
        float p  = fminf(offset + ls[j], npmf);
        float pf = floorf(p);
        float w  = p - pf;
        uint32_t pv = tab2u[(int)pf];
        float2 f = __half22float2(*(__half2*)&pv);
        oo[j] = fmaf(w, f.y - f.x, f.x);
    }

    float* orow = out + (size_t)row * K_DIM + tid * 8;
    *(float4*)(orow)     = make_float4(oo[0], oo[1], oo[2], oo[3]);
    *(float4*)(orow + 4) = make_float4(oo[4], oo[5], oo[6], oo[7]);
}

// ---------------------------------------------------------------------------
extern "C" void kernel_launch(void* const* d_in, const int* in_sizes, int n_in,
                              void* d_out, int out_size) {
    const float* q    = (const float*)d_in[0];   // [B,H,Q,D]
    const float* attn = (const float*)d_in[1];   // [B,H,Q,K]
    const float* pe   = (const float*)d_in[2];   // [1,D,NPOS]
    const int*   npos = (const int*)d_in[3];
    float*       out  = (float*)d_out;

    const int R = in_sizes[0] / D_DIM;           // 49152

    cudaFuncSetAttribute(cope_gemm_mma,
                         cudaFuncAttributeMaxDynamicSharedMemorySize, SM_TOTAL);
    dim3 gA(NPOS / 256, R / 128);
    cope_gemm_mma<<<gA, 512, SM_TOTAL>>>(q, pe);

    cope_gather_kernel<<<R, 256>>>(attn, npos, out);

    (void)n_in; (void)out_size;
}